// round 16
// baseline (speedup 1.0000x reference)
#include <cuda_runtime.h>
#include <stdint.h>

#define NN 100000
#define EE 1600000
#define DD 64

#define SCAN_BS 1024
#define SCAN_NB ((NN + SCAN_BS - 1) / SCAN_BS)   // 98

// ---------------- device scratch (static; no allocation) ----------------
__device__ int   g_flag64;
__device__ int   g_deg[NN];
__device__ int   g_fill[NN];
__device__ int   g_rowptr[NN + 1];
__device__ int   g_blocksums[128];
__device__ int   g_cols[EE];
__device__ int2  g_wc[EE];            // packed (col, w-bits) for SpMV
__device__ float g_q[NN * DD];
__device__ float g_k[NN * DD];
__device__ float g_scores[EE * 4];    // pass1: scores; pass2 onward: exp values
__device__ float g_meanatt[EE];
__device__ float g_yv[NN * DD];
__device__ float g_stA[NN * DD];
__device__ float g_stB[NN * DD];
__device__ float g_stC[NN * DD];
// radix select state
__device__ unsigned g_hist[256];
__device__ unsigned g_selPrefix;
__device__ unsigned g_selRank;
__device__ unsigned g_selResult[2];
__device__ unsigned g_cntLE;
__device__ unsigned g_minGt;
__device__ unsigned g_cand[EE];
__device__ unsigned g_candCnt;
__device__ unsigned g_cumBelow;
__device__ unsigned g_minGtHigh;

// ---------------- fused init: zero counts + hist + select state + detect ---
__global__ void k_init(const int* ei32) {
    int i = blockIdx.x * blockDim.x + threadIdx.x;
    if (i < NN) { g_deg[i] = 0; g_fill[i] = 0; }
    if (i < 256) g_hist[i] = 0;
    if (i == 0) {
        g_selPrefix = 0;
        g_selRank = 79999u;
        g_cntLE = 0;
        g_minGt = 0xFFFFFFFFu;
        g_candCnt = 0;
        g_cumBelow = 0;
        g_minGtHigh = 0xFFFFFFFFu;
    }
    if (blockIdx.x == 0) {
        int v = 0;
        #pragma unroll
        for (int j = 0; j < 8; j++)
            v |= ei32[2 * (threadIdx.x * 8 + j) + 1];
        int any = __syncthreads_or(v != 0);
        if (threadIdx.x == 0) g_flag64 = (any == 0) ? 1 : 0;
    }
}

// ---------------- CSR build (2 edges per thread) ----------------
__global__ void k_count2(const void* ei) {
    int i = blockIdx.x * blockDim.x + threadIdx.x;
    if (i >= EE / 2) return;
    int r0, r1;
    if (g_flag64) {
        longlong2 rr = ((const longlong2*)ei)[i];
        r0 = (int)rr.x; r1 = (int)rr.y;
    } else {
        int2 rr = ((const int2*)ei)[i];
        r0 = rr.x; r1 = rr.y;
    }
    atomicAdd(&g_deg[r0], 1);
    atomicAdd(&g_deg[r1], 1);
}

__global__ void k_scan1() {
    __shared__ int sh[SCAN_BS];
    int t = threadIdx.x;
    int i = blockIdx.x * SCAN_BS + t;
    int v = (i < NN) ? g_deg[i] : 0;
    sh[t] = v;
    __syncthreads();
    for (int off = 1; off < SCAN_BS; off <<= 1) {
        int x = (t >= off) ? sh[t - off] : 0;
        __syncthreads();
        if (t >= off) sh[t] += x;
        __syncthreads();
    }
    if (i < NN) g_rowptr[i] = sh[t] - v;
    if (t == SCAN_BS - 1) g_blocksums[blockIdx.x] = sh[t];
}

__global__ void k_scan2() {
    __shared__ int sh[128];
    int t = threadIdx.x;
    int v = (t < SCAN_NB) ? g_blocksums[t] : 0;
    sh[t] = v;
    __syncthreads();
    for (int off = 1; off < 128; off <<= 1) {
        int x = (t >= off) ? sh[t - off] : 0;
        __syncthreads();
        if (t >= off) sh[t] += x;
        __syncthreads();
    }
    if (t < SCAN_NB) g_blocksums[t] = sh[t] - v;
    if (t == 0) g_rowptr[NN] = EE;
}

__global__ void k_scan3() {
    int i = blockIdx.x * blockDim.x + threadIdx.x;
    if (i < NN) g_rowptr[i] += g_blocksums[i >> 10];
}

__global__ void k_scatter2(const void* ei) {
    int i = blockIdx.x * blockDim.x + threadIdx.x;
    if (i >= EE / 2) return;
    int r0, r1, c0, c1;
    if (g_flag64) {
        const long long* p = (const long long*)ei;
        longlong2 rr = ((const longlong2*)p)[i];
        longlong2 cc = ((const longlong2*)(p + EE))[i];
        r0 = (int)rr.x; r1 = (int)rr.y;
        c0 = (int)cc.x; c1 = (int)cc.y;
    } else {
        const int* p = (const int*)ei;
        int2 rr = ((const int2*)p)[i];
        int2 cc = ((const int2*)(p + EE))[i];
        r0 = rr.x; r1 = rr.y;
        c0 = cc.x; c1 = cc.y;
    }
    g_cols[g_rowptr[r0] + atomicAdd(&g_fill[r0], 1)] = c0;
    g_cols[g_rowptr[r1] + atomicAdd(&g_fill[r1], 1)] = c1;
}

// ---------------- q/k GEMM: 16 rows per block ----------------
__global__ __launch_bounds__(256) void k_gemm(const float* __restrict__ x,
                                              const float* __restrict__ Wq,
                                              const float* __restrict__ Wk) {
    __shared__ float sWq[64 * 64];
    __shared__ float sWk[64 * 64];
    __shared__ float sX[16 * 64];
    int tid = threadIdx.x;
    for (int i = tid; i < 4096; i += 256) { sWq[i] = Wq[i]; sWk[i] = Wk[i]; }
    int rbase = blockIdx.x * 16;
    for (int i = tid; i < 1024; i += 256) sX[i] = x[rbase * 64 + i];
    __syncthreads();
    int q = tid >> 6;
    int c = tid & 63;
    float aq[4] = {0.f, 0.f, 0.f, 0.f};
    float ak[4] = {0.f, 0.f, 0.f, 0.f};
    #pragma unroll
    for (int t = 0; t < 64; t++) {
        float wq = sWq[t * 64 + c];
        float wk = sWk[t * 64 + c];
        #pragma unroll
        for (int j = 0; j < 4; j++) {
            float xv = sX[(q + 4 * j) * 64 + t];
            aq[j] = fmaf(xv, wq, aq[j]);
            ak[j] = fmaf(xv, wk, ak[j]);
        }
    }
    #pragma unroll
    for (int j = 0; j < 4; j++) {
        g_q[(rbase + q + 4 * j) * 64 + c] = aq[j];
        g_k[(rbase + q + 4 * j) * 64 + c] = ak[j];
    }
}

__device__ __forceinline__ float warp_sum(float v) {
    #pragma unroll
    for (int o = 16; o; o >>= 1) v += __shfl_xor_sync(0xFFFFFFFFu, v, o);
    return v;
}

// ---------------- fused attention: scores + softmaxA + top-byte hist -------
__global__ __launch_bounds__(256) void k_att() {
    __shared__ unsigned shH[256];
    int tid = threadIdx.x;
    shH[tid] = 0;
    __syncthreads();

    int gw = (blockIdx.x * blockDim.x + tid) >> 5;
    int lane = tid & 31;
    int s = g_rowptr[gw], e = g_rowptr[gw + 1];

    if (s < e) {
        int eoff = lane >> 2;      // 0..7: edge within batch of 8
        int h    = lane & 3;       // head

        const float4* qb = (const float4*)(g_q + (size_t)gw * 64 + h * 16);
        float4 q0 = qb[0], q1 = qb[1], q2 = qb[2], q3 = qb[3];

        float mh = -1e30f;
        for (int bj = s; bj < e; bj += 8) {
            int j = bj + eoff;
            bool valid = j < e;
            int col = valid ? g_cols[j] : 0;
            const float4* kb = (const float4*)(g_k + (size_t)col * 64 + h * 16);
            float4 k0 = kb[0], k1 = kb[1], k2 = kb[2], k3 = kb[3];
            float p = q0.x * k0.x;
            p = fmaf(q0.y, k0.y, p); p = fmaf(q0.z, k0.z, p); p = fmaf(q0.w, k0.w, p);
            p = fmaf(q1.x, k1.x, p); p = fmaf(q1.y, k1.y, p);
            p = fmaf(q1.z, k1.z, p); p = fmaf(q1.w, k1.w, p);
            p = fmaf(q2.x, k2.x, p); p = fmaf(q2.y, k2.y, p);
            p = fmaf(q2.z, k2.z, p); p = fmaf(q2.w, k2.w, p);
            p = fmaf(q3.x, k3.x, p); p = fmaf(q3.y, k3.y, p);
            p = fmaf(q3.z, k3.z, p); p = fmaf(q3.w, k3.w, p);
            float sc = p * 0.25f;              // 1/sqrt(16)
            if (valid) {
                mh = fmaxf(mh, sc);
                g_scores[(size_t)j * 4 + h] = sc;
            }
        }
        mh = fmaxf(mh, __shfl_xor_sync(0xFFFFFFFFu, mh, 4));
        mh = fmaxf(mh, __shfl_xor_sync(0xFFFFFFFFu, mh, 8));
        mh = fmaxf(mh, __shfl_xor_sync(0xFFFFFFFFu, mh, 16));
        float m0 = __shfl_sync(0xFFFFFFFFu, mh, 0);
        float m1 = __shfl_sync(0xFFFFFFFFu, mh, 1);
        float m2 = __shfl_sync(0xFFFFFFFFu, mh, 2);
        float m3 = __shfl_sync(0xFFFFFFFFu, mh, 3);

        float t0 = 0.f, t1 = 0.f, t2 = 0.f, t3 = 0.f;
        for (int j = s + lane; j < e; j += 32) {
            float4 sc = ((const float4*)g_scores)[j];
            float4 ex;
            ex.x = __expf(sc.x - m0); ex.y = __expf(sc.y - m1);
            ex.z = __expf(sc.z - m2); ex.w = __expf(sc.w - m3);
            ((float4*)g_scores)[j] = ex;
            t0 += ex.x; t1 += ex.y; t2 += ex.z; t3 += ex.w;
        }
        t0 = warp_sum(t0) + 1e-16f; t1 = warp_sum(t1) + 1e-16f;
        t2 = warp_sum(t2) + 1e-16f; t3 = warp_sum(t3) + 1e-16f;
        float r0 = 1.f / t0, r1 = 1.f / t1, r2 = 1.f / t2, r3 = 1.f / t3;
        for (int j = s + lane; j < e; j += 32) {
            float4 ex = ((const float4*)g_scores)[j];
            float me = 0.25f * (ex.x * r0 + ex.y * r1 + ex.z * r2 + ex.w * r3);
            g_meanatt[j] = me;
            atomicAdd(&shH[__float_as_uint(me) >> 24], 1u);
        }
    }
    __syncthreads();
    if (shH[tid]) atomicAdd(&g_hist[tid], shH[tid]);
}

// ---------------- pick 1: choose top byte, record cum-below ----------------
__global__ void k_sel_pick1() {
    unsigned rank = g_selRank;
    unsigned cum = 0;
    int chosen = 255;
    for (int b = 0; b < 256; b++) {
        unsigned h = g_hist[b];
        if (rank < cum + h) { chosen = b; break; }
        cum += h;
    }
    g_selRank = rank - cum;
    g_cumBelow = cum;
    g_selPrefix = ((unsigned)chosen) << 24;
}

// ---------------- compact chosen-bucket values + min of higher buckets -----
__global__ __launch_bounds__(256) void k_compact() {
    unsigned pre = g_selPrefix;          // chosen byte << 24
    unsigned mnHigh = 0xFFFFFFFFu;
    for (int e = blockIdx.x * blockDim.x + threadIdx.x; e < EE;
         e += gridDim.x * blockDim.x) {
        unsigned u = __float_as_uint(g_meanatt[e]);
        unsigned top = u & 0xFF000000u;
        bool inB = (top == pre);
        unsigned mask = __ballot_sync(0xFFFFFFFFu, inB);
        if (inB) {
            unsigned base = 0;
            int leader = __ffs(mask) - 1;
            if ((int)(threadIdx.x & 31) == leader)
                base = atomicAdd(&g_candCnt, __popc(mask));
            base = __shfl_sync(mask, base, leader);   // member mask = inB lanes
            unsigned off = __popc(mask & ((1u << (threadIdx.x & 31)) - 1u));
            g_cand[base + off] = u;
        } else if (top > pre) {
            mnHigh = min(mnHigh, u);
        }
    }
    #pragma unroll
    for (int o = 16; o; o >>= 1)
        mnHigh = min(mnHigh, __shfl_xor_sync(0xFFFFFFFFu, mnHigh, o));
    if ((threadIdx.x & 31) == 0 && mnHigh != 0xFFFFFFFFu)
        atomicMin(&g_minGtHigh, mnHigh);
}

// ---------------- finisher: radix passes 2-4 + successor, one block --------
__global__ __launch_bounds__(1024) void k_finish() {
    __shared__ unsigned hist[256];
    __shared__ unsigned shPrefix;
    __shared__ unsigned shRank;
    __shared__ unsigned shCnt;
    __shared__ unsigned shMin;
    int tid = threadIdx.x;
    unsigned cnt = g_candCnt;
    if (tid == 0) {
        shPrefix = g_selPrefix;
        shRank = g_selRank;
        shCnt = 0;
        shMin = 0xFFFFFFFFu;
    }
    __syncthreads();

    unsigned mask = 0xFF000000u;
    for (int shf = 16; shf >= 0; shf -= 8) {
        if (tid < 256) hist[tid] = 0;
        __syncthreads();
        unsigned pre = shPrefix;
        for (unsigned i = tid; i < cnt; i += 1024) {
            unsigned u = g_cand[i];
            if ((u & mask) == pre)
                atomicAdd(&hist[(u >> shf) & 255], 1u);
        }
        __syncthreads();
        if (tid == 0) {
            unsigned rank = shRank;
            unsigned cum = 0;
            int chosen = 255;
            for (int b = 0; b < 256; b++) {
                unsigned h = hist[b];
                if (rank < cum + h) { chosen = b; break; }
                cum += h;
            }
            shRank = rank - cum;
            shPrefix = pre | (((unsigned)chosen) << shf);
        }
        __syncthreads();
        mask |= 0xFFu << shf;
    }

    unsigned v0 = shPrefix;
    unsigned myCnt = 0;
    unsigned myMin = 0xFFFFFFFFu;
    for (unsigned i = tid; i < cnt; i += 1024) {
        unsigned u = g_cand[i];
        if (u <= v0) myCnt++;
        else myMin = min(myMin, u);
    }
    #pragma unroll
    for (int o = 16; o; o >>= 1) {
        myCnt += __shfl_xor_sync(0xFFFFFFFFu, myCnt, o);
        myMin = min(myMin, __shfl_xor_sync(0xFFFFFFFFu, myMin, o));
    }
    if ((tid & 31) == 0) {
        atomicAdd(&shCnt, myCnt);
        atomicMin(&shMin, myMin);
    }
    __syncthreads();
    if (tid == 0) {
        g_selResult[0] = v0;
        g_cntLE = g_cumBelow + shCnt;
        g_minGt = min(shMin, g_minGtHigh);
    }
}

// ---------------- masked re-softmax -> packed edge weights -----------------
__global__ __launch_bounds__(256) void k_wmask() {
    int gw = (blockIdx.x * blockDim.x + threadIdx.x) >> 5;
    if (gw >= NN) return;
    int lane = threadIdx.x & 31;
    int s = g_rowptr[gw], e = g_rowptr[gw + 1];
    float v0 = __uint_as_float(g_selResult[0]);          // v[79999]
    float v1 = (g_cntLE >= 80001u) ? v0
             : __uint_as_float(g_minGt);                 // v[80000]
    float thr = v0 * 0.046875f + v1 * 0.953125f;
    float t0 = 0.f, t1 = 0.f, t2 = 0.f, t3 = 0.f;
    for (int j = s + lane; j < e; j += 32) {
        if (g_meanatt[j] > thr) {
            float4 ex = ((const float4*)g_scores)[j];
            t0 += ex.x; t1 += ex.y; t2 += ex.z; t3 += ex.w;
        }
    }
    t0 = warp_sum(t0) + 1e-16f; t1 = warp_sum(t1) + 1e-16f;
    t2 = warp_sum(t2) + 1e-16f; t3 = warp_sum(t3) + 1e-16f;
    float r0 = 1.f / t0, r1 = 1.f / t1, r2 = 1.f / t2, r3 = 1.f / t3;
    for (int j = s + lane; j < e; j += 32) {
        float wv = 0.f;
        if (g_meanatt[j] > thr) {
            float4 ex = ((const float4*)g_scores)[j];
            wv = 0.25f * (ex.x * r0 + ex.y * r1 + ex.z * r2 + ex.w * r3);
        }
        g_wc[j] = make_int2(g_cols[j], __float_as_int(wv));
    }
}

// ---------------- RK4 SpMV: 2 edges/iter, float4 gathers, NO accumulator ---
__global__ __launch_bounds__(256) void k_spmv(const float* __restrict__ yin,
                                              const float* __restrict__ base,
                                              float* __restrict__ nxt,
                                              float coefNext,
                                              int finalMode,
                                              const float* __restrict__ pA,
                                              const float* __restrict__ pB,
                                              float dt6) {
    __shared__ int2 stage[8][32];
    int gw = (blockIdx.x * blockDim.x + threadIdx.x) >> 5;
    if (gw >= NN) return;
    int wib = (threadIdx.x >> 5) & 7;
    int lane = threadIdx.x & 31;
    int half = lane >> 4;           // 0: even edge, 1: odd edge
    int quad = lane & 15;           // float4 index within the 64-float row
    int s = g_rowptr[gw], e = g_rowptr[gw + 1];
    const float4* y4 = (const float4*)yin;
    float ax = 0.f, ay = 0.f, az = 0.f, aw = 0.f;
    for (int bj = s; bj < e; bj += 32) {
        int idx = bj + lane;
        int2 m = (idx < e) ? g_wc[idx] : make_int2(0, 0);
        __syncwarp();
        stage[wib][lane] = m;
        __syncwarp();
        int kmax = e - bj;
        if (kmax > 32) kmax = 32;
        const int2* st = stage[wib];
        #pragma unroll 4
        for (int k = 0; k < kmax; k += 2) {
            int2 mk = st[k + half];
            float wk = __int_as_float(mk.y);
            float4 fv = y4[((size_t)(unsigned)mk.x << 4) + quad];
            ax = fmaf(wk, fv.x, ax);
            ay = fmaf(wk, fv.y, ay);
            az = fmaf(wk, fv.z, az);
            aw = fmaf(wk, fv.w, aw);
        }
    }
    ax += __shfl_xor_sync(0xFFFFFFFFu, ax, 16);
    ay += __shfl_xor_sync(0xFFFFFFFFu, ay, 16);
    az += __shfl_xor_sync(0xFFFFFFFFu, az, 16);
    aw += __shfl_xor_sync(0xFFFFFFFFu, aw, 16);
    if (lane < 16) {
        size_t qidx = (size_t)gw * 16 + quad;
        float4 yb = y4[qidx];           // diag term (stage4: stC value)
        float f0 = ax - yb.x;
        float f1 = ay - yb.y;
        float f2 = az - yb.z;
        float f3 = aw - yb.w;
        float4 bb = ((const float4*)base)[qidx];   // y
        float4 r;
        if (finalMode) {
            float4 va = ((const float4*)pA)[qidx]; // stA
            float4 vb = ((const float4*)pB)[qidx]; // stB
            r.x = bb.x + dt6 * (8.f * (va.x - bb.x) + 16.f * (vb.x - bb.x) +
                                 8.f * (yb.x - bb.x) + f0);
            r.y = bb.y + dt6 * (8.f * (va.y - bb.y) + 16.f * (vb.y - bb.y) +
                                 8.f * (yb.y - bb.y) + f1);
            r.z = bb.z + dt6 * (8.f * (va.z - bb.z) + 16.f * (vb.z - bb.z) +
                                 8.f * (yb.z - bb.z) + f2);
            r.w = bb.w + dt6 * (8.f * (va.w - bb.w) + 16.f * (vb.w - bb.w) +
                                 8.f * (yb.w - bb.w) + f3);
        } else {
            r.x = bb.x + coefNext * f0;
            r.y = bb.y + coefNext * f1;
            r.z = bb.z + coefNext * f2;
            r.w = bb.w + coefNext * f3;
        }
        ((float4*)nxt)[qidx] = r;
    }
}

// ---------------- host launch ----------------
static float* s_yv  = nullptr;
static float* s_stA = nullptr;
static float* s_stB = nullptr;
static float* s_stC = nullptr;

static void resolve_symbols() {
    if (!s_yv) {
        cudaGetSymbolAddress((void**)&s_yv,  g_yv);
        cudaGetSymbolAddress((void**)&s_stA, g_stA);
        cudaGetSymbolAddress((void**)&s_stB, g_stB);
        cudaGetSymbolAddress((void**)&s_stC, g_stC);
    }
}

extern "C" void kernel_launch(void* const* d_in, const int* in_sizes, int n_in,
                              void* d_out, int out_size) {
    (void)out_size;
    resolve_symbols();

    const float* x = nullptr;
    const void*  ei = nullptr;
    const float* Wq = nullptr;
    const float* Wk = nullptr;
    for (int i = 0; i < n_in; i++) {
        if (in_sizes[i] == 2 * EE) ei = d_in[i];
        else if (in_sizes[i] == NN * DD) x = (const float*)d_in[i];
        else if (in_sizes[i] == DD * DD) {
            if (!Wq) Wq = (const float*)d_in[i];
            else     Wk = (const float*)d_in[i];
        }
    }
    float* out = (float*)d_out;

    int grid = (NN * 32 + 255) / 256;
    int gridW = (NN + 7) / 8;
    int gridE2 = (EE / 2 + 255) / 256;

    const float dt   = 0.25f;
    const float half = 0.125f;
    const float dt6  = 0.25f / 6.0f;

    k_init<<<(NN + 255) / 256, 256>>>((const int*)ei);
    k_count2<<<gridE2, 256>>>(ei);
    k_scan1<<<SCAN_NB, SCAN_BS>>>();
    k_scan2<<<1, 128>>>();
    k_scan3<<<SCAN_NB, SCAN_BS>>>();
    k_scatter2<<<gridE2, 256>>>(ei);

    k_gemm<<<NN / 16, 256>>>(x, Wq, Wk);
    k_att<<<gridW, 256>>>();               // also builds the shift-24 hist

    // fused radix select: pick top byte, compact bucket, finish in one block
    k_sel_pick1<<<1, 1>>>();
    k_compact<<<1024, 256>>>();
    k_finish<<<1, 1024>>>();

    k_wmask<<<gridW, 256>>>();             // thr computed inline

    // RK4 without an accumulator buffer. Step 0 reads y0 = x directly.
    for (int step = 0; step < 4; step++) {
        const float* ycur = (step == 0) ? x : s_yv;
        float* finalDst = (step == 3) ? out : s_yv;
        k_spmv<<<grid, 256>>>(ycur,  ycur, s_stA, half, 0, nullptr, nullptr, dt6);
        k_spmv<<<grid, 256>>>(s_stA, ycur, s_stB, half, 0, nullptr, nullptr, dt6);
        k_spmv<<<grid, 256>>>(s_stB, ycur, s_stC, dt,   0, nullptr, nullptr, dt6);
        k_spmv<<<grid, 256>>>(s_stC, ycur, finalDst, 0.f, 1, s_stA, s_stB, dt6);
    }
}

// round 17
// speedup vs baseline: 1.0776x; 1.0776x over previous
#include <cuda_runtime.h>
#include <stdint.h>

#define NN 100000
#define EE 1600000
#define DD 64

#define SCAN_BS 1024
#define SCAN_NB ((NN + SCAN_BS - 1) / SCAN_BS)   // 98

// ---------------- device scratch (static; no allocation) ----------------
__device__ int   g_flag64;
__device__ int   g_deg[NN];
__device__ int   g_fill[NN];
__device__ int   g_rowptr[NN + 1];
__device__ int   g_blocksums[128];
__device__ int   g_cols[EE];
__device__ int2  g_wc[EE];            // packed (col, w-bits) for SpMV
__device__ float g_q[NN * DD];
__device__ float g_k[NN * DD];
__device__ float g_scores[EE * 4];    // pass1: scores; pass2 onward: exp values
__device__ float g_meanatt[EE];
__device__ float g_yv[NN * DD];
__device__ float g_stA[NN * DD];
__device__ float g_stB[NN * DD];
__device__ float g_stC[NN * DD];
// radix select state
__device__ unsigned g_hist[256];
__device__ unsigned g_selPrefix;
__device__ unsigned g_selMask;
__device__ int      g_selShift;
__device__ unsigned g_selRank;
__device__ unsigned g_selResult[2];
__device__ unsigned g_cntLE;
__device__ unsigned g_minGt;

// ---------------- fused init: zero counts + hist + select state + detect ---
__global__ void k_init(const int* ei32) {
    int i = blockIdx.x * blockDim.x + threadIdx.x;
    if (i < NN) { g_deg[i] = 0; g_fill[i] = 0; }
    if (i < 256) g_hist[i] = 0;
    if (i == 0) {
        g_selShift = 24;
        g_selPrefix = 0;
        g_selMask = 0;
        g_selRank = 79999u;
        g_cntLE = 0;
        g_minGt = 0xFFFFFFFFu;
    }
    if (blockIdx.x == 0) {
        int v = 0;
        #pragma unroll
        for (int j = 0; j < 8; j++)
            v |= ei32[2 * (threadIdx.x * 8 + j) + 1];
        int any = __syncthreads_or(v != 0);
        if (threadIdx.x == 0) g_flag64 = (any == 0) ? 1 : 0;
    }
}

// ---------------- CSR build (2 edges per thread) ----------------
__global__ void k_count2(const void* ei) {
    int i = blockIdx.x * blockDim.x + threadIdx.x;
    if (i >= EE / 2) return;
    int r0, r1;
    if (g_flag64) {
        longlong2 rr = ((const longlong2*)ei)[i];
        r0 = (int)rr.x; r1 = (int)rr.y;
    } else {
        int2 rr = ((const int2*)ei)[i];
        r0 = rr.x; r1 = rr.y;
    }
    atomicAdd(&g_deg[r0], 1);
    atomicAdd(&g_deg[r1], 1);
}

__global__ void k_scan1() {
    __shared__ int sh[SCAN_BS];
    int t = threadIdx.x;
    int i = blockIdx.x * SCAN_BS + t;
    int v = (i < NN) ? g_deg[i] : 0;
    sh[t] = v;
    __syncthreads();
    for (int off = 1; off < SCAN_BS; off <<= 1) {
        int x = (t >= off) ? sh[t - off] : 0;
        __syncthreads();
        if (t >= off) sh[t] += x;
        __syncthreads();
    }
    if (i < NN) g_rowptr[i] = sh[t] - v;
    if (t == SCAN_BS - 1) g_blocksums[blockIdx.x] = sh[t];
}

__global__ void k_scan2() {
    __shared__ int sh[128];
    int t = threadIdx.x;
    int v = (t < SCAN_NB) ? g_blocksums[t] : 0;
    sh[t] = v;
    __syncthreads();
    for (int off = 1; off < 128; off <<= 1) {
        int x = (t >= off) ? sh[t - off] : 0;
        __syncthreads();
        if (t >= off) sh[t] += x;
        __syncthreads();
    }
    if (t < SCAN_NB) g_blocksums[t] = sh[t] - v;
    if (t == 0) g_rowptr[NN] = EE;
}

__global__ void k_scan3() {
    int i = blockIdx.x * blockDim.x + threadIdx.x;
    if (i < NN) g_rowptr[i] += g_blocksums[i >> 10];
}

__global__ void k_scatter2(const void* ei) {
    int i = blockIdx.x * blockDim.x + threadIdx.x;
    if (i >= EE / 2) return;
    int r0, r1, c0, c1;
    if (g_flag64) {
        const long long* p = (const long long*)ei;
        longlong2 rr = ((const longlong2*)p)[i];
        longlong2 cc = ((const longlong2*)(p + EE))[i];
        r0 = (int)rr.x; r1 = (int)rr.y;
        c0 = (int)cc.x; c1 = (int)cc.y;
    } else {
        const int* p = (const int*)ei;
        int2 rr = ((const int2*)p)[i];
        int2 cc = ((const int2*)(p + EE))[i];
        r0 = rr.x; r1 = rr.y;
        c0 = cc.x; c1 = cc.y;
    }
    g_cols[g_rowptr[r0] + atomicAdd(&g_fill[r0], 1)] = c0;
    g_cols[g_rowptr[r1] + atomicAdd(&g_fill[r1], 1)] = c1;
}

// ---------------- q/k GEMM: 16 rows per block ----------------
__global__ __launch_bounds__(256) void k_gemm(const float* __restrict__ x,
                                              const float* __restrict__ Wq,
                                              const float* __restrict__ Wk) {
    __shared__ float sWq[64 * 64];
    __shared__ float sWk[64 * 64];
    __shared__ float sX[16 * 64];
    int tid = threadIdx.x;
    for (int i = tid; i < 4096; i += 256) { sWq[i] = Wq[i]; sWk[i] = Wk[i]; }
    int rbase = blockIdx.x * 16;
    for (int i = tid; i < 1024; i += 256) sX[i] = x[rbase * 64 + i];
    __syncthreads();
    int q = tid >> 6;
    int c = tid & 63;
    float aq[4] = {0.f, 0.f, 0.f, 0.f};
    float ak[4] = {0.f, 0.f, 0.f, 0.f};
    #pragma unroll
    for (int t = 0; t < 64; t++) {
        float wq = sWq[t * 64 + c];
        float wk = sWk[t * 64 + c];
        #pragma unroll
        for (int j = 0; j < 4; j++) {
            float xv = sX[(q + 4 * j) * 64 + t];
            aq[j] = fmaf(xv, wq, aq[j]);
            ak[j] = fmaf(xv, wk, ak[j]);
        }
    }
    #pragma unroll
    for (int j = 0; j < 4; j++) {
        g_q[(rbase + q + 4 * j) * 64 + c] = aq[j];
        g_k[(rbase + q + 4 * j) * 64 + c] = ak[j];
    }
}

__device__ __forceinline__ float warp_sum(float v) {
    #pragma unroll
    for (int o = 16; o; o >>= 1) v += __shfl_xor_sync(0xFFFFFFFFu, v, o);
    return v;
}

// ---------------- fused attention: scores + softmaxA + top-byte hist -------
__global__ __launch_bounds__(256) void k_att() {
    __shared__ unsigned shH[256];
    int tid = threadIdx.x;
    shH[tid] = 0;
    __syncthreads();

    int gw = (blockIdx.x * blockDim.x + tid) >> 5;
    int lane = tid & 31;
    int s = g_rowptr[gw], e = g_rowptr[gw + 1];

    if (s < e) {
        int eoff = lane >> 2;      // 0..7: edge within batch of 8
        int h    = lane & 3;       // head

        const float4* qb = (const float4*)(g_q + (size_t)gw * 64 + h * 16);
        float4 q0 = qb[0], q1 = qb[1], q2 = qb[2], q3 = qb[3];

        float mh = -1e30f;
        for (int bj = s; bj < e; bj += 8) {
            int j = bj + eoff;
            bool valid = j < e;
            int col = valid ? g_cols[j] : 0;
            const float4* kb = (const float4*)(g_k + (size_t)col * 64 + h * 16);
            float4 k0 = kb[0], k1 = kb[1], k2 = kb[2], k3 = kb[3];
            float p = q0.x * k0.x;
            p = fmaf(q0.y, k0.y, p); p = fmaf(q0.z, k0.z, p); p = fmaf(q0.w, k0.w, p);
            p = fmaf(q1.x, k1.x, p); p = fmaf(q1.y, k1.y, p);
            p = fmaf(q1.z, k1.z, p); p = fmaf(q1.w, k1.w, p);
            p = fmaf(q2.x, k2.x, p); p = fmaf(q2.y, k2.y, p);
            p = fmaf(q2.z, k2.z, p); p = fmaf(q2.w, k2.w, p);
            p = fmaf(q3.x, k3.x, p); p = fmaf(q3.y, k3.y, p);
            p = fmaf(q3.z, k3.z, p); p = fmaf(q3.w, k3.w, p);
            float sc = p * 0.25f;              // 1/sqrt(16)
            if (valid) {
                mh = fmaxf(mh, sc);
                g_scores[(size_t)j * 4 + h] = sc;
            }
        }
        mh = fmaxf(mh, __shfl_xor_sync(0xFFFFFFFFu, mh, 4));
        mh = fmaxf(mh, __shfl_xor_sync(0xFFFFFFFFu, mh, 8));
        mh = fmaxf(mh, __shfl_xor_sync(0xFFFFFFFFu, mh, 16));
        float m0 = __shfl_sync(0xFFFFFFFFu, mh, 0);
        float m1 = __shfl_sync(0xFFFFFFFFu, mh, 1);
        float m2 = __shfl_sync(0xFFFFFFFFu, mh, 2);
        float m3 = __shfl_sync(0xFFFFFFFFu, mh, 3);

        float t0 = 0.f, t1 = 0.f, t2 = 0.f, t3 = 0.f;
        for (int j = s + lane; j < e; j += 32) {
            float4 sc = ((const float4*)g_scores)[j];
            float4 ex;
            ex.x = __expf(sc.x - m0); ex.y = __expf(sc.y - m1);
            ex.z = __expf(sc.z - m2); ex.w = __expf(sc.w - m3);
            ((float4*)g_scores)[j] = ex;
            t0 += ex.x; t1 += ex.y; t2 += ex.z; t3 += ex.w;
        }
        t0 = warp_sum(t0) + 1e-16f; t1 = warp_sum(t1) + 1e-16f;
        t2 = warp_sum(t2) + 1e-16f; t3 = warp_sum(t3) + 1e-16f;
        float r0 = 1.f / t0, r1 = 1.f / t1, r2 = 1.f / t2, r3 = 1.f / t3;
        for (int j = s + lane; j < e; j += 32) {
            float4 ex = ((const float4*)g_scores)[j];
            float me = 0.25f * (ex.x * r0 + ex.y * r1 + ex.z * r2 + ex.w * r3);
            g_meanatt[j] = me;
            atomicAdd(&shH[__float_as_uint(me) >> 24], 1u);
        }
    }
    __syncthreads();
    if (shH[tid]) atomicAdd(&g_hist[tid], shH[tid]);
}

// ---------------- exact radix select (rank 79999) + successor ----------------
__global__ void k_sel_hist() {
    __shared__ unsigned sh[256];
    int t = threadIdx.x;
    sh[t] = 0;
    __syncthreads();
    int shf = g_selShift;
    unsigned pre = g_selPrefix, msk = g_selMask;
    for (int e = blockIdx.x * blockDim.x + t; e < EE; e += gridDim.x * blockDim.x) {
        unsigned u = __float_as_uint(g_meanatt[e]);
        if ((u & msk) == pre) atomicAdd(&sh[(u >> shf) & 255], 1u);
    }
    __syncthreads();
    if (sh[t]) atomicAdd(&g_hist[t], sh[t]);
}

// parallel pick: 256 threads, shared inclusive scan, then zero hist
__global__ __launch_bounds__(256) void k_sel_pick() {
    __shared__ unsigned sh[256];
    __shared__ int shChosen;
    int t = threadIdx.x;
    unsigned h = g_hist[t];
    sh[t] = h;
    if (t == 0) shChosen = 255;
    __syncthreads();
    // inclusive scan over 256 bins
    for (int off = 1; off < 256; off <<= 1) {
        unsigned x = (t >= off) ? sh[t - off] : 0u;
        __syncthreads();
        sh[t] += x;
        __syncthreads();
    }
    unsigned rank = g_selRank;
    unsigned incl = sh[t];
    unsigned excl = incl - h;
    if (rank < incl && rank >= excl) shChosen = t;   // unique t satisfies this
    __syncthreads();
    int chosen = shChosen;
    if (t == 0) {
        unsigned cum = (chosen > 0) ? sh[chosen - 1] : 0u;
        int shf = g_selShift;
        g_selRank = rank - cum;
        g_selPrefix |= ((unsigned)chosen) << shf;
        g_selMask |= 0xFFu << shf;
        g_selShift = shf - 8;
        if (shf == 0) g_selResult[0] = g_selPrefix;
    }
    g_hist[t] = 0;
}

__global__ __launch_bounds__(256) void k_succ() {
    __shared__ unsigned shCnt;
    __shared__ unsigned shMin;
    if (threadIdx.x == 0) { shCnt = 0; shMin = 0xFFFFFFFFu; }
    __syncthreads();
    unsigned v0 = g_selResult[0];
    unsigned cnt = 0;
    unsigned mn = 0xFFFFFFFFu;
    for (int e = blockIdx.x * blockDim.x + threadIdx.x; e < EE;
         e += gridDim.x * blockDim.x) {
        unsigned u = __float_as_uint(g_meanatt[e]);
        if (u <= v0) cnt++;
        else mn = min(mn, u);
    }
    #pragma unroll
    for (int o = 16; o; o >>= 1) {
        cnt += __shfl_xor_sync(0xFFFFFFFFu, cnt, o);
        mn = min(mn, __shfl_xor_sync(0xFFFFFFFFu, mn, o));
    }
    if ((threadIdx.x & 31) == 0) {
        atomicAdd(&shCnt, cnt);
        atomicMin(&shMin, mn);
    }
    __syncthreads();
    if (threadIdx.x == 0) {
        atomicAdd(&g_cntLE, shCnt);
        atomicMin(&g_minGt, shMin);
    }
}

// ---------------- masked re-softmax -> packed edge weights -----------------
__global__ __launch_bounds__(256) void k_wmask() {
    int gw = (blockIdx.x * blockDim.x + threadIdx.x) >> 5;
    if (gw >= NN) return;
    int lane = threadIdx.x & 31;
    int s = g_rowptr[gw], e = g_rowptr[gw + 1];
    float v0 = __uint_as_float(g_selResult[0]);          // v[79999]
    float v1 = (g_cntLE >= 80001u) ? v0
             : __uint_as_float(g_minGt);                 // v[80000]
    float thr = v0 * 0.046875f + v1 * 0.953125f;
    float t0 = 0.f, t1 = 0.f, t2 = 0.f, t3 = 0.f;
    for (int j = s + lane; j < e; j += 32) {
        if (g_meanatt[j] > thr) {
            float4 ex = ((const float4*)g_scores)[j];
            t0 += ex.x; t1 += ex.y; t2 += ex.z; t3 += ex.w;
        }
    }
    t0 = warp_sum(t0) + 1e-16f; t1 = warp_sum(t1) + 1e-16f;
    t2 = warp_sum(t2) + 1e-16f; t3 = warp_sum(t3) + 1e-16f;
    float r0 = 1.f / t0, r1 = 1.f / t1, r2 = 1.f / t2, r3 = 1.f / t3;
    for (int j = s + lane; j < e; j += 32) {
        float wv = 0.f;
        if (g_meanatt[j] > thr) {
            float4 ex = ((const float4*)g_scores)[j];
            wv = 0.25f * (ex.x * r0 + ex.y * r1 + ex.z * r2 + ex.w * r3);
        }
        g_wc[j] = make_int2(g_cols[j], __float_as_int(wv));
    }
}

// ---------------- RK4 SpMV: 2 edges/iter, float4 gathers, NO accumulator ---
__global__ __launch_bounds__(256) void k_spmv(const float* __restrict__ yin,
                                              const float* __restrict__ base,
                                              float* __restrict__ nxt,
                                              float coefNext,
                                              int finalMode,
                                              const float* __restrict__ pA,
                                              const float* __restrict__ pB,
                                              float dt6) {
    __shared__ int2 stage[8][32];
    int gw = (blockIdx.x * blockDim.x + threadIdx.x) >> 5;
    if (gw >= NN) return;
    int wib = (threadIdx.x >> 5) & 7;
    int lane = threadIdx.x & 31;
    int half = lane >> 4;           // 0: even edge, 1: odd edge
    int quad = lane & 15;           // float4 index within the 64-float row
    int s = g_rowptr[gw], e = g_rowptr[gw + 1];
    const float4* y4 = (const float4*)yin;
    float ax = 0.f, ay = 0.f, az = 0.f, aw = 0.f;
    for (int bj = s; bj < e; bj += 32) {
        int idx = bj + lane;
        int2 m = (idx < e) ? g_wc[idx] : make_int2(0, 0);
        __syncwarp();
        stage[wib][lane] = m;
        __syncwarp();
        int kmax = e - bj;
        if (kmax > 32) kmax = 32;
        const int2* st = stage[wib];
        #pragma unroll 4
        for (int k = 0; k < kmax; k += 2) {
            int2 mk = st[k + half];
            float wk = __int_as_float(mk.y);
            float4 fv = y4[((size_t)(unsigned)mk.x << 4) + quad];
            ax = fmaf(wk, fv.x, ax);
            ay = fmaf(wk, fv.y, ay);
            az = fmaf(wk, fv.z, az);
            aw = fmaf(wk, fv.w, aw);
        }
    }
    ax += __shfl_xor_sync(0xFFFFFFFFu, ax, 16);
    ay += __shfl_xor_sync(0xFFFFFFFFu, ay, 16);
    az += __shfl_xor_sync(0xFFFFFFFFu, az, 16);
    aw += __shfl_xor_sync(0xFFFFFFFFu, aw, 16);
    if (lane < 16) {
        size_t qidx = (size_t)gw * 16 + quad;
        float4 yb = y4[qidx];           // diag term (stage4: stC value)
        float f0 = ax - yb.x;
        float f1 = ay - yb.y;
        float f2 = az - yb.z;
        float f3 = aw - yb.w;
        float4 bb = ((const float4*)base)[qidx];   // y
        float4 r;
        if (finalMode) {
            float4 va = ((const float4*)pA)[qidx]; // stA
            float4 vb = ((const float4*)pB)[qidx]; // stB
            r.x = bb.x + dt6 * (8.f * (va.x - bb.x) + 16.f * (vb.x - bb.x) +
                                 8.f * (yb.x - bb.x) + f0);
            r.y = bb.y + dt6 * (8.f * (va.y - bb.y) + 16.f * (vb.y - bb.y) +
                                 8.f * (yb.y - bb.y) + f1);
            r.z = bb.z + dt6 * (8.f * (va.z - bb.z) + 16.f * (vb.z - bb.z) +
                                 8.f * (yb.z - bb.z) + f2);
            r.w = bb.w + dt6 * (8.f * (va.w - bb.w) + 16.f * (vb.w - bb.w) +
                                 8.f * (yb.w - bb.w) + f3);
        } else {
            r.x = bb.x + coefNext * f0;
            r.y = bb.y + coefNext * f1;
            r.z = bb.z + coefNext * f2;
            r.w = bb.w + coefNext * f3;
        }
        ((float4*)nxt)[qidx] = r;
    }
}

// ---------------- host launch ----------------
static float* s_yv  = nullptr;
static float* s_stA = nullptr;
static float* s_stB = nullptr;
static float* s_stC = nullptr;

static void resolve_symbols() {
    if (!s_yv) {
        cudaGetSymbolAddress((void**)&s_yv,  g_yv);
        cudaGetSymbolAddress((void**)&s_stA, g_stA);
        cudaGetSymbolAddress((void**)&s_stB, g_stB);
        cudaGetSymbolAddress((void**)&s_stC, g_stC);
    }
}

extern "C" void kernel_launch(void* const* d_in, const int* in_sizes, int n_in,
                              void* d_out, int out_size) {
    (void)out_size;
    resolve_symbols();

    const float* x = nullptr;
    const void*  ei = nullptr;
    const float* Wq = nullptr;
    const float* Wk = nullptr;
    for (int i = 0; i < n_in; i++) {
        if (in_sizes[i] == 2 * EE) ei = d_in[i];
        else if (in_sizes[i] == NN * DD) x = (const float*)d_in[i];
        else if (in_sizes[i] == DD * DD) {
            if (!Wq) Wq = (const float*)d_in[i];
            else     Wk = (const float*)d_in[i];
        }
    }
    float* out = (float*)d_out;

    int grid = (NN * 32 + 255) / 256;
    int gridW = (NN + 7) / 8;
    int gridE2 = (EE / 2 + 255) / 256;

    const float dt   = 0.25f;
    const float half = 0.125f;
    const float dt6  = 0.25f / 6.0f;

    k_init<<<(NN + 255) / 256, 256>>>((const int*)ei);
    k_count2<<<gridE2, 256>>>(ei);
    k_scan1<<<SCAN_NB, SCAN_BS>>>();
    k_scan2<<<1, 128>>>();
    k_scan3<<<SCAN_NB, SCAN_BS>>>();
    k_scatter2<<<gridE2, 256>>>(ei);

    k_gemm<<<NN / 16, 256>>>(x, Wq, Wk);
    k_att<<<gridW, 256>>>();               // also builds the shift-24 hist

    // radix select (R14 structure, parallel picks)
    k_sel_pick<<<1, 256>>>();
    for (int p = 0; p < 3; p++) {
        k_sel_hist<<<1024, 256>>>();
        k_sel_pick<<<1, 256>>>();
    }
    k_succ<<<1024, 256>>>();

    k_wmask<<<gridW, 256>>>();             // thr computed inline

    // RK4 without an accumulator buffer. Step 0 reads y0 = x directly.
    for (int step = 0; step < 4; step++) {
        const float* ycur = (step == 0) ? x : s_yv;
        float* finalDst = (step == 3) ? out : s_yv;
        k_spmv<<<grid, 256>>>(ycur,  ycur, s_stA, half, 0, nullptr, nullptr, dt6);
        k_spmv<<<grid, 256>>>(s_stA, ycur, s_stB, half, 0, nullptr, nullptr, dt6);
        k_spmv<<<grid, 256>>>(s_stB, ycur, s_stC, dt,   0, nullptr, nullptr, dt6);
        k_spmv<<<grid, 256>>>(s_stC, ycur, finalDst, 0.f, 1, s_stA, s_stB, dt6);
    }
}